// round 12
// baseline (speedup 1.0000x reference)
#include <cuda_runtime.h>
#include <cuda_bf16.h>
#include <math.h>
#include <stdint.h>

// ContrastiveLoss, bf16 HMMA Gram matrix, A-resident tiling + 2-deep cp.async
// B prefetch + algebraic fast-path hinge epilogue with exact per-thread
// fallback (folded COUPLE_BOOST). 3 launches:
//
//  prep_kernel : 4 rows/warp (MLP 8), normalize, emit bf16 E,
//                cp = s+2eps*r+d*eps^2, cm = s-2eps*r, label-dtype sniff,
//                reset pattern flag + completion counter.
//  lab_kernel  : flatten labels to int32; verify alternating 0,1 pattern.
//  pair_kernel : persistent; contiguous row-major triangular 128x128 tile
//                ranges (A resident), B double-buffered via cp.async 2 tiles
//                ahead, 16 k-steps ldmatrix + mma.sync bf16, fast/exact
//                fused hinge epilogue, per-CTA double partial; LAST block
//                (atomic counter) reduces partials in fixed order and
//                writes the scalar.

#define D      256
#define N_MAX  8192
#define EPSV   1e-6f
#define TM     128
#define GRID_PAIR 148

__device__ __nv_bfloat16 g_ebf[N_MAX * D];
__device__ float  g_cp[N_MAX];
__device__ float  g_cm[N_MAX];
__device__ int    g_lab[N_MAX];
__device__ int    g_is64;
__device__ int    g_pat;
__device__ int    g_cnt;
__device__ double g_part[GRID_PAIR];

__device__ __forceinline__ uint32_t smem_u32(const void* p) {
    uint32_t a;
    asm("{ .reg .u64 t; cvta.to.shared.u64 t, %1; cvt.u32.u64 %0, t; }"
        : "=r"(a) : "l"(p));
    return a;
}
__device__ __forceinline__ void ldsm4(uint32_t* r, uint32_t a) {
    asm volatile("ldmatrix.sync.aligned.m8n8.x4.shared.b16 {%0,%1,%2,%3}, [%4];"
                 : "=r"(r[0]), "=r"(r[1]), "=r"(r[2]), "=r"(r[3]) : "r"(a));
}
__device__ __forceinline__ void mma16816(float* c, const uint32_t* a,
                                         uint32_t b0, uint32_t b1) {
    asm volatile(
        "mma.sync.aligned.m16n8k16.row.col.f32.bf16.bf16.f32 "
        "{%0,%1,%2,%3}, {%4,%5,%6,%7}, {%8,%9}, {%0,%1,%2,%3};"
        : "+f"(c[0]), "+f"(c[1]), "+f"(c[2]), "+f"(c[3])
        : "r"(a[0]), "r"(a[1]), "r"(a[2]), "r"(a[3]), "r"(b0), "r"(b1));
}
__device__ __forceinline__ float fast_sqrt(float x) {
    float r;
    asm("sqrt.approx.f32 %0, %1;" : "=f"(r) : "f"(x));
    return r;
}
__device__ __forceinline__ void cpasync16(uint32_t dst, const void* src) {
    asm volatile("cp.async.cg.shared.global [%0], [%1], 16;"
                 :: "r"(dst), "l"(src) : "memory");
}
#define CP_COMMIT() asm volatile("cp.async.commit_group;" ::: "memory")
#define CP_WAIT1()  asm volatile("cp.async.wait_group 1;" ::: "memory")

// SMEM layout: A resident 64K | B buf0 64K | B buf1 64K | stats 2x2K
#define OFF_A   0
#define OFF_B0  65536
#define OFF_B1  131072
#define OFF_ST  196608
#define SMEM_BYTES (196608 + 4096)

// ---------------------------------------------------------------------------
// prep: 4 rows per warp, all loads issued up front (MLP 8 per thread)
__global__ void prep_kernel(const float* __restrict__ x,
                            const int* __restrict__ lab32, int n) {
    int wid = threadIdx.x >> 5, lid = threadIdx.x & 31;
    int row0 = blockIdx.x * 32 + wid * 4;

    int rows[4];
    float4 va[4], vb[4];
#pragma unroll
    for (int r = 0; r < 4; r++) {
        rows[r] = min(row0 + r, n - 1);
        const float4* src = (const float4*)&x[rows[r] * D + lid * 8];
        va[r] = src[0];
        vb[r] = src[1];
    }
    float ss[4], sv[4];
#pragma unroll
    for (int r = 0; r < 4; r++) {
        float4 a = va[r], b = vb[r];
        ss[r] = a.x*a.x + a.y*a.y + a.z*a.z + a.w*a.w
              + b.x*b.x + b.y*b.y + b.z*b.z + b.w*b.w;
        sv[r] = a.x + a.y + a.z + a.w + b.x + b.y + b.z + b.w;
    }
#pragma unroll
    for (int o = 16; o > 0; o >>= 1) {
#pragma unroll
        for (int r = 0; r < 4; r++) {
            ss[r] += __shfl_xor_sync(0xffffffffu, ss[r], o);
            sv[r] += __shfl_xor_sync(0xffffffffu, sv[r], o);
        }
    }
#pragma unroll
    for (int r = 0; r < 4; r++) {
        float inv = 1.0f / fmaxf(sqrtf(ss[r]), EPSV);
        float4 a = va[r], b = vb[r];
        __nv_bfloat162 w0 = __nv_bfloat162(__float2bfloat16(a.x*inv), __float2bfloat16(a.y*inv));
        __nv_bfloat162 w1 = __nv_bfloat162(__float2bfloat16(a.z*inv), __float2bfloat16(a.w*inv));
        __nv_bfloat162 w2 = __nv_bfloat162(__float2bfloat16(b.x*inv), __float2bfloat16(b.y*inv));
        __nv_bfloat162 w3 = __nv_bfloat162(__float2bfloat16(b.z*inv), __float2bfloat16(b.w*inv));
        uint4 pk;
        pk.x = *(uint32_t*)&w0; pk.y = *(uint32_t*)&w1;
        pk.z = *(uint32_t*)&w2; pk.w = *(uint32_t*)&w3;
        *(uint4*)&g_ebf[rows[r] * D + lid * 8] = pk;
        if (lid == 0) {
            float s = ss[r] * inv * inv, rr = sv[r] * inv;
            g_cp[rows[r]] = s + 2.0f * EPSV * rr + (float)D * EPSV * EPSV;
            g_cm[rows[r]] = s - 2.0f * EPSV * rr;
        }
    }

    if (blockIdx.x == 0 && threadIdx.x == 0) { g_pat = 1; g_cnt = 0; }
    // label dtype sniff: int64 storage iff all high words are 0.
    // Only first n/2 labels checked -> in-bounds under both interpretations.
    if (blockIdx.x == 0) {
        __shared__ int sh_ok;
        if (threadIdx.x == 0) sh_ok = 1;
        __syncthreads();
        int ok = 1;
        for (int idx = threadIdx.x; idx < n / 2; idx += blockDim.x)
            if (lab32[2 * idx + 1] != 0) ok = 0;
        if (!ok) atomicAnd(&sh_ok, 0);
        __syncthreads();
        if (threadIdx.x == 0) g_is64 = sh_ok;
    }
}

__global__ void lab_kernel(const int* __restrict__ lab32, int n) {
    int i = blockIdx.x * blockDim.x + threadIdx.x;
    if (i < n) {
        int v = lab32[g_is64 ? 2 * i : i];
        g_lab[i] = v;
        if (v != (i & 1)) atomicAnd(&g_pat, 0);   // verify alternating pattern
    }
}

// ---------------------------------------------------------------------------
__device__ __forceinline__ void decode_tile(int t, int& i0, int& j0) {
    int bi = (int)((sqrtf(8.0f * (float)t + 1.0f) - 1.0f) * 0.5f);
    while ((bi + 1) * (bi + 2) / 2 <= t) bi++;
    while (bi * (bi + 1) / 2 > t) bi--;
    i0 = bi * TM;
    j0 = (t - bi * (bi + 1) / 2) * TM;
}

// exact epilogue: sum of h^2 (0.5 deferred) + folded partner-boost extra h^2.
// Partner pair I==J+1 (lab[I]==1, labels differ) lives in exactly one tile:
// tile-local condition jj == ii + didx with didx = i0 - j0 - 1.
template<bool MASK, bool FAST>
__device__ __forceinline__ float epilogue(const float (&cacc)[2][8][4],
                                          const char* sb, int warp_m, int warp_n,
                                          int lid, int i0, int j0, int n) {
    const float* cpv = (const float*)sb;
    const float* cmv = (const float*)(sb + 512);
    const int*   liv = (const int*)(sb + 1024);
    const int*   ljv = (const int*)(sb + 1536);
    const int rbase = lid >> 2, cbase = (lid & 3) << 1;
    const int pi = rbase & 1;
    const int didx = i0 - j0 - 1;

    float cj[16]; int lj[16];
#pragma unroll
    for (int k = 0; k < 16; k++) {
        int jj = warp_n * 64 + (k >> 1) * 8 + cbase + (k & 1);
        cj[k] = cmv[jj];
        if (!FAST) lj[k] = ljv[jj];
    }
    const float se0 = (pi == 0) ? 1.0f : -1.0f;
    const float ce0 = (pi == 0) ? -0.1f : 1.0f;
    const float se1 = -se0;
    const float ce1 = (pi == 0) ? 1.0f : -0.1f;

    float ls0 = 0.f, ls1 = 0.f, ls2 = 0.f, ls3 = 0.f;
#pragma unroll
    for (int mt = 0; mt < 2; mt++)
#pragma unroll
    for (int half = 0; half < 2; half++) {
        int ii = warp_m * 32 + mt * 16 + rbase + half * 8;
        float ci = cpv[ii];
        int li = 0;
        if (!FAST) li = liv[ii];
        const int jtarget = ii + didx;
        const bool brow = FAST ? (((i0 + ii) & 1) == 1) : (li == 1);
#pragma unroll
        for (int nt = 0; nt < 8; nt++)
#pragma unroll
        for (int e = 0; e < 2; e++) {
            int jj = warp_n * 64 + nt * 8 + cbase + e;
            float g = cacc[mt][nt][half * 2 + e];
            float d2 = fmaf(g, -2.0f, ci + cj[nt * 2 + e]);
            float d  = fast_sqrt(fmaxf(d2, 1e-12f));
            float h;
            bool boosted;
            if (FAST) {
                h = fmaf(d, e ? se1 : se0, e ? ce1 : ce0);
                boosted = brow && (jj == jtarget);
            } else {
                int ljv2 = lj[nt * 2 + e];
                h = (li == ljv2) ? (d - 0.1f) : (1.0f - d);
                boosted = brow && (li != ljv2) && (jj == jtarget);
            }
            h = fmaxf(h, 0.0f);
            if (MASK) {
                int I = i0 + ii, J = j0 + jj;
                h = (I > J && I < n) ? h : 0.0f;
            }
            float hh = h * h;
            if (e) ls1 += hh; else ls0 += hh;
            if (boosted) { if (e) ls3 += hh; else ls2 += hh; }
        }
    }
    return (ls0 + ls1) + (ls2 + ls3);
}

// fast epilogue (off-diagonal tiles, alternating labels): per thread there
// are 32 pos-parity slots (mt*half*nt) and 32 neg slots. Assumes every neg
// slot inactive (d2 >= 1) and every pos slot unclipped (d2 >= 0.01); verified
// by fmin chains, exact per-thread fallback otherwise. Boost pairs are neg
// pairs -> only matter when a neg slot is active -> covered by fallback.
__device__ __forceinline__ float epi_fast(const float (&cacc)[2][8][4],
                                          const char* sb, int warp_m, int warp_n,
                                          int lid, int i0, int j0, int n) {
    const float* cpv = (const float*)sb;
    const float* cmv = (const float*)(sb + 512);
    const int rbase = lid >> 2, cbase = (lid & 3) << 1;
    const int pi = rbase & 1;

    float cj[16];
#pragma unroll
    for (int k = 0; k < 16; k++)
        cj[k] = cmv[warp_n * 64 + (k >> 1) * 8 + cbase + (k & 1)];

    float td0 = 0.f, td1 = 0.f, t2a = 0.f, t2b = 0.f;
    float mnp = 1e30f, mnn = 1e30f;
#pragma unroll
    for (int mt = 0; mt < 2; mt++)
#pragma unroll
    for (int half = 0; half < 2; half++) {
        int ii = warp_m * 32 + mt * 16 + rbase + half * 8;
        float ci = cpv[ii];
#pragma unroll
        for (int nt = 0; nt < 8; nt++) {
            float g0 = cacc[mt][nt][half * 2 + 0];
            float g1 = cacc[mt][nt][half * 2 + 1];
            float d20 = fmaf(g0, -2.0f, ci + cj[nt * 2 + 0]);
            float d21 = fmaf(g1, -2.0f, ci + cj[nt * 2 + 1]);
            float d2p = pi ? d21 : d20;     // pos slot: e parity == pi
            float d2n = pi ? d20 : d21;
            mnp = fminf(mnp, d2p);
            mnn = fminf(mnn, d2n);
            d2p = fmaxf(d2p, 1e-12f);
            if (nt & 1) { td1 += fast_sqrt(d2p); t2b += d2p; }
            else        { td0 += fast_sqrt(d2p); t2a += d2p; }
        }
    }
    if (mnp < 0.01f || mnn < 1.0f)          // rare: exact per-thread redo
        return epilogue<false, true>(cacc, sb, warp_m, warp_n, lid, i0, j0, n);
    // 32 pos slots: sum (d-0.1)^2 = sum d2 - 0.2*sum d + 32*0.01
    return fmaf(td0 + td1, -0.2f, t2a + t2b) + 0.32f;
}

__global__ void __launch_bounds__(256, 1)
pair_kernel(float* __restrict__ out, int n, int ntiles, int gp) {
    extern __shared__ char sm[];
    const uint32_t smb = smem_u32(sm);

    const int tid = threadIdx.x, wid = tid >> 5, lid = tid & 31;
    const int warp_m = wid >> 1, warp_n = wid & 1;
    const int q = lid >> 3, rl = lid & 7;
    const int qh = q >> 1, ql = q & 1;
    const int pat = g_pat;
    const bool nmask_all = (n & (TM - 1)) != 0;

    uint32_t rowA[2], r7A[2];
#pragma unroll
    for (int mt = 0; mt < 2; mt++) {
        int r = warp_m * 32 + mt * 16 + ql * 8 + rl;
        rowA[mt] = (uint32_t)r << 9;
        r7A[mt]  = (uint32_t)(r & 7);
    }
    uint32_t rowB[4], r7B[4];
#pragma unroll
    for (int p = 0; p < 4; p++) {
        int r = warp_n * 64 + p * 16 + qh * 8 + rl;
        rowB[p] = (uint32_t)r << 9;
        r7B[p]  = (uint32_t)(r & 7);
    }

    auto load_tile = [&](uint32_t dstbase, int row0) {
#pragma unroll
        for (int k = 0; k < 16; k++) {
            int idx = tid + (k << 8);
            int r = idx >> 5, c = idx & 31;
            uint32_t soff = ((uint32_t)r << 9) + (uint32_t)((c ^ (r & 7)) << 4);
            int gr = min(row0 + r, n - 1);
            cpasync16(dstbase + soff, &g_ebf[gr * D + (c << 3)]);
        }
    };
    auto load_stats = [&](int i0, int j0, int par) {
        if (tid < 128) {
            uint32_t sb = smb + OFF_ST + (uint32_t)par * 2048u;
            int grp = tid >> 5, l = tid & 31;
            const void* src;
            if      (grp == 0) src = &g_cp[min(i0 + l * 4, n - 4)];
            else if (grp == 1) src = &g_cm[min(j0 + l * 4, n - 4)];
            else if (grp == 2) src = &g_lab[min(i0 + l * 4, n - 4)];
            else               src = &g_lab[min(j0 + l * 4, n - 4)];
            cpasync16(sb + (uint32_t)grp * 512u + (uint32_t)l * 16u, src);
        }
    };

    const int base = ntiles / gp, rem = ntiles % gp;
    const int bid = blockIdx.x;
    const int tstart = bid * base + min(bid, rem);
    const int len = base + (bid < rem ? 1 : 0);
    const int tend = tstart + len;

    // ---- prologue ----
    int i0, j0, ni0 = 0, nj0 = 0;
    decode_tile(tstart, i0, j0);
    load_tile(smb + OFF_A, i0);
    load_tile(smb + OFF_B0, j0);
    load_stats(i0, j0, 0);
    CP_COMMIT();
    if (tstart + 1 < tend) {
        decode_tile(tstart + 1, ni0, nj0);
        load_tile(smb + OFF_B1, nj0);
        load_stats(ni0, nj0, 1);
    }
    CP_COMMIT();

    double acc = 0.0;
    for (int it = 0; it < len; it++) {
        const int t = tstart + it;
        CP_WAIT1();
        __syncthreads();

        const uint32_t Ab = smb + OFF_A;
        const uint32_t Bb = smb + ((it & 1) ? OFF_B1 : OFF_B0);

        float cacc[2][8][4];
#pragma unroll
        for (int mt = 0; mt < 2; mt++)
#pragma unroll
            for (int nt = 0; nt < 8; nt++)
#pragma unroll
                for (int e = 0; e < 4; e++) cacc[mt][nt][e] = 0.0f;

#pragma unroll
        for (int ks = 0; ks < 16; ks++) {
            const uint32_t cb = (uint32_t)(ks << 1);
            uint32_t Af[2][4];
#pragma unroll
            for (int mt = 0; mt < 2; mt++)
                ldsm4(Af[mt], Ab + rowA[mt] + (((cb + qh) ^ r7A[mt]) << 4));
#pragma unroll
            for (int p = 0; p < 4; p++) {
                uint32_t Bf[4];
                ldsm4(Bf, Bb + rowB[p] + (((cb + ql) ^ r7B[p]) << 4));
                mma16816(cacc[0][2 * p],     Af[0], Bf[0], Bf[1]);
                mma16816(cacc[1][2 * p],     Af[1], Bf[0], Bf[1]);
                mma16816(cacc[0][2 * p + 1], Af[0], Bf[2], Bf[3]);
                mma16816(cacc[1][2 * p + 1], Af[1], Bf[2], Bf[3]);
            }
        }

        {
            const char* sb = sm + OFF_ST + (size_t)(it & 1) * 2048;
            bool mask = (i0 == j0) || nmask_all;
            float lsum;
            if (pat) {
                if (mask) lsum = epilogue<true, true>(cacc, sb, warp_m, warp_n, lid, i0, j0, n);
                else      lsum = epi_fast(cacc, sb, warp_m, warp_n, lid, i0, j0, n);
            } else {
                lsum = mask ? epilogue<true,  false>(cacc, sb, warp_m, warp_n, lid, i0, j0, n)
                            : epilogue<false, false>(cacc, sb, warp_m, warp_n, lid, i0, j0, n);
            }
            acc += (double)lsum;
        }

        __syncthreads();

        if (it + 1 < len && ni0 != i0) load_tile(smb + OFF_A, ni0);
        CP_COMMIT();
        int m0 = 0, mj0 = 0;
        if ((t + 2) < tend) {
            decode_tile(t + 2, m0, mj0);
            load_tile(smb + ((it & 1) ? OFF_B1 : OFF_B0), mj0);
            load_stats(m0, mj0, it & 1);
        }
        CP_COMMIT();

        i0 = ni0; j0 = nj0;
        ni0 = m0; nj0 = mj0;
    }

    // ---- deterministic per-CTA reduction ----
#pragma unroll
    for (int o = 16; o > 0; o >>= 1)
        acc += __shfl_xor_sync(0xffffffffu, acc, o);
    __shared__ double sh_d[8];
    __shared__ int sh_last;
    if (lid == 0) sh_d[wid] = acc;
    __syncthreads();
    if (tid == 0) {
        double tot = 0.0;
#pragma unroll
        for (int w = 0; w < 8; w++) tot += sh_d[w];
        g_part[bid] = tot;
        __threadfence();
        unsigned old = atomicAdd((unsigned*)&g_cnt, 1u);
        sh_last = (old == (unsigned)(gp - 1));
    }
    __syncthreads();

    // ---- last block: final reduction (fixed order -> deterministic) ----
    if (sh_last) {
        __threadfence();
        double s = 0.0;
        for (int i = tid; i < gp; i += 256) s += __ldcg(&g_part[i]);
#pragma unroll
        for (int o = 16; o > 0; o >>= 1)
            s += __shfl_xor_sync(0xffffffffu, s, o);
        if (lid == 0) sh_d[wid] = s;
        __syncthreads();
        if (tid == 0) {
            double tot = 0.0;
#pragma unroll
            for (int w = 0; w < 8; w++) tot += sh_d[w];
            out[0] = (float)(0.5 * tot / (0.5 * (double)n * (double)(n - 1)));
        }
    }
}

// ---------------------------------------------------------------------------
extern "C" void kernel_launch(void* const* d_in, const int* in_sizes, int n_in,
                              void* d_out, int out_size) {
    const float* emb = (const float*)d_in[0];
    const int*   lab = (const int*)d_in[1];   // dtype sniffed on-device
    int n = in_sizes[0] / D;

    cudaFuncSetAttribute(pair_kernel, cudaFuncAttributeMaxDynamicSharedMemorySize, SMEM_BYTES);

    prep_kernel<<<(n + 31) / 32, 256>>>(emb, lab, n);
    lab_kernel<<<(n + 255) / 256, 256>>>(lab, n);

    int nb = (n + TM - 1) / TM;
    int ntiles = nb * (nb + 1) / 2;
    int gp = min(GRID_PAIR, ntiles);
    pair_kernel<<<gp, 256, SMEM_BYTES>>>((float*)d_out, n, ntiles, gp);
}

// round 13
// speedup vs baseline: 1.1568x; 1.1568x over previous
#include <cuda_runtime.h>
#include <cuda_bf16.h>
#include <math.h>
#include <stdint.h>

// ContrastiveLoss, bf16 HMMA Gram matrix, A-resident tiling + 2-deep cp.async
// B prefetch + algebraic fast-path hinge epilogue with exact per-thread
// fallback (folded COUPLE_BOOST). 3 launches:
//
//  prep_kernel : normalize rows, emit bf16 E, cp = s+2eps*r+d*eps^2,
//                cm = s-2eps*r. First 32 blocks additionally: per-block
//                label-dtype sniff (int64 vs int32 storage), flatten their
//                1/32 label slice to g_lab, verify alternating 0,1 pattern
//                into g_patv[b] (written every launch -> no init race).
//  pair_kernel : persistent; contiguous row-major triangular 128x128 tile
//                ranges (A resident), B double-buffered via cp.async 2 tiles
//                ahead, 16 k-steps ldmatrix + mma.sync bf16, fast/exact
//                fused hinge epilogue, per-CTA double partial.
//                (Body frozen at the 74.75us R10 state.)
//  finalize    : deterministic reduce, total = 0.5*parts/ncomp.

#define D      256
#define N_MAX  8192
#define EPSV   1e-6f
#define TM     128
#define GRID_PAIR 148
#define NFBMAX 32

__device__ __nv_bfloat16 g_ebf[N_MAX * D];
__device__ float  g_cp[N_MAX];
__device__ float  g_cm[N_MAX];
__device__ int    g_lab[N_MAX];
__device__ int    g_patv[NFBMAX];
__device__ double g_part[GRID_PAIR];

__device__ __forceinline__ uint32_t smem_u32(const void* p) {
    uint32_t a;
    asm("{ .reg .u64 t; cvta.to.shared.u64 t, %1; cvt.u32.u64 %0, t; }"
        : "=r"(a) : "l"(p));
    return a;
}
__device__ __forceinline__ void ldsm4(uint32_t* r, uint32_t a) {
    asm volatile("ldmatrix.sync.aligned.m8n8.x4.shared.b16 {%0,%1,%2,%3}, [%4];"
                 : "=r"(r[0]), "=r"(r[1]), "=r"(r[2]), "=r"(r[3]) : "r"(a));
}
__device__ __forceinline__ void mma16816(float* c, const uint32_t* a,
                                         uint32_t b0, uint32_t b1) {
    asm volatile(
        "mma.sync.aligned.m16n8k16.row.col.f32.bf16.bf16.f32 "
        "{%0,%1,%2,%3}, {%4,%5,%6,%7}, {%8,%9}, {%0,%1,%2,%3};"
        : "+f"(c[0]), "+f"(c[1]), "+f"(c[2]), "+f"(c[3])
        : "r"(a[0]), "r"(a[1]), "r"(a[2]), "r"(a[3]), "r"(b0), "r"(b1));
}
__device__ __forceinline__ float fast_sqrt(float x) {
    float r;
    asm("sqrt.approx.f32 %0, %1;" : "=f"(r) : "f"(x));
    return r;
}
__device__ __forceinline__ void cpasync16(uint32_t dst, const void* src) {
    asm volatile("cp.async.cg.shared.global [%0], [%1], 16;"
                 :: "r"(dst), "l"(src) : "memory");
}
#define CP_COMMIT() asm volatile("cp.async.commit_group;" ::: "memory")
#define CP_WAIT1()  asm volatile("cp.async.wait_group 1;" ::: "memory")

// SMEM layout: A resident 64K | B buf0 64K | B buf1 64K | stats 2x2K
#define OFF_A   0
#define OFF_B0  65536
#define OFF_B1  131072
#define OFF_ST  196608
#define SMEM_BYTES (196608 + 4096)

__host__ __device__ static inline int nfb_of(int n) {
    int nb = (n + 7) / 8;                 // prep grid size
    return nb < NFBMAX ? nb : NFBMAX;
}

// ---------------------------------------------------------------------------
// prep: one row per warp, 8 rows/block; first nfb blocks also handle labels.
__global__ void prep_kernel(const float* __restrict__ x,
                            const int* __restrict__ lab32, int n) {
    int wid = threadIdx.x >> 5, lid = threadIdx.x & 31;
    int row = blockIdx.x * 8 + wid;
    if (row < n) {
        const float4* src = (const float4*)&x[row * D + lid * 8];
        float4 a = src[0], b = src[1];
        float ss = a.x*a.x + a.y*a.y + a.z*a.z + a.w*a.w
                 + b.x*b.x + b.y*b.y + b.z*b.z + b.w*b.w;
        float sv = a.x + a.y + a.z + a.w + b.x + b.y + b.z + b.w;
#pragma unroll
        for (int o = 16; o > 0; o >>= 1) {
            ss += __shfl_xor_sync(0xffffffffu, ss, o);
            sv += __shfl_xor_sync(0xffffffffu, sv, o);
        }
        float inv = 1.0f / fmaxf(sqrtf(ss), EPSV);
        __nv_bfloat162 w0 = __nv_bfloat162(__float2bfloat16(a.x*inv), __float2bfloat16(a.y*inv));
        __nv_bfloat162 w1 = __nv_bfloat162(__float2bfloat16(a.z*inv), __float2bfloat16(a.w*inv));
        __nv_bfloat162 w2 = __nv_bfloat162(__float2bfloat16(b.x*inv), __float2bfloat16(b.y*inv));
        __nv_bfloat162 w3 = __nv_bfloat162(__float2bfloat16(b.z*inv), __float2bfloat16(b.w*inv));
        uint4 pk;
        pk.x = *(uint32_t*)&w0; pk.y = *(uint32_t*)&w1;
        pk.z = *(uint32_t*)&w2; pk.w = *(uint32_t*)&w3;
        *(uint4*)&g_ebf[row * D + lid * 8] = pk;
        if (lid == 0) {
            float s = ss * inv * inv, r = sv * inv;
            g_cp[row] = s + 2.0f * EPSV * r + (float)D * EPSV * EPSV;
            g_cm[row] = s - 2.0f * EPSV * r;
        }
    }

    // Label handling in the first nfb blocks, each fully independent:
    // per-block dtype sniff (int64 storage iff all high words of the first
    // n/2 labels are 0 -> reads in-bounds under both interpretations), then
    // flatten this block's 1/32 slice and verify the alternating pattern.
    const int nfb = nfb_of(n);
    if ((int)blockIdx.x < nfb) {
        __shared__ int sh_ok;
        if (threadIdx.x == 0) sh_ok = 1;
        __syncthreads();
        int ok = 1;
        for (int idx = threadIdx.x; idx < n / 2; idx += blockDim.x)
            if (lab32[2 * idx + 1] != 0) ok = 0;
        if (!ok) atomicAnd(&sh_ok, 0);
        __syncthreads();
        const int is64 = sh_ok;

        int patok = 1;
        const int stride = nfb * blockDim.x;
        for (int i = blockIdx.x * blockDim.x + threadIdx.x; i < n; i += stride) {
            int v = lab32[is64 ? 2 * i : i];
            g_lab[i] = v;
            if (v != (i & 1)) patok = 0;
        }
        // block-reduce patok (reuse sh_ok slot after a sync)
        __syncthreads();
        if (threadIdx.x == 0) sh_ok = 1;
        __syncthreads();
        if (!patok) atomicAnd(&sh_ok, 0);
        __syncthreads();
        if (threadIdx.x == 0) g_patv[blockIdx.x] = sh_ok;
    }
}

// ---------------------------------------------------------------------------
__device__ __forceinline__ void decode_tile(int t, int& i0, int& j0) {
    int bi = (int)((sqrtf(8.0f * (float)t + 1.0f) - 1.0f) * 0.5f);
    while ((bi + 1) * (bi + 2) / 2 <= t) bi++;
    while (bi * (bi + 1) / 2 > t) bi--;
    i0 = bi * TM;
    j0 = (t - bi * (bi + 1) / 2) * TM;
}

// exact epilogue: sum of h^2 (0.5 deferred) + folded partner-boost extra h^2.
// Partner pair I==J+1 (lab[I]==1, labels differ) lives in exactly one tile:
// tile-local condition jj == ii + didx with didx = i0 - j0 - 1.
template<bool MASK, bool FAST>
__device__ __forceinline__ float epilogue(const float (&cacc)[2][8][4],
                                          const char* sb, int warp_m, int warp_n,
                                          int lid, int i0, int j0, int n) {
    const float* cpv = (const float*)sb;
    const float* cmv = (const float*)(sb + 512);
    const int*   liv = (const int*)(sb + 1024);
    const int*   ljv = (const int*)(sb + 1536);
    const int rbase = lid >> 2, cbase = (lid & 3) << 1;
    const int pi = rbase & 1;
    const int didx = i0 - j0 - 1;

    float cj[16]; int lj[16];
#pragma unroll
    for (int k = 0; k < 16; k++) {
        int jj = warp_n * 64 + (k >> 1) * 8 + cbase + (k & 1);
        cj[k] = cmv[jj];
        if (!FAST) lj[k] = ljv[jj];
    }
    const float se0 = (pi == 0) ? 1.0f : -1.0f;
    const float ce0 = (pi == 0) ? -0.1f : 1.0f;
    const float se1 = -se0;
    const float ce1 = (pi == 0) ? 1.0f : -0.1f;

    float ls0 = 0.f, ls1 = 0.f, ls2 = 0.f, ls3 = 0.f;
#pragma unroll
    for (int mt = 0; mt < 2; mt++)
#pragma unroll
    for (int half = 0; half < 2; half++) {
        int ii = warp_m * 32 + mt * 16 + rbase + half * 8;
        float ci = cpv[ii];
        int li = 0;
        if (!FAST) li = liv[ii];
        const int jtarget = ii + didx;
        const bool brow = FAST ? (((i0 + ii) & 1) == 1) : (li == 1);
#pragma unroll
        for (int nt = 0; nt < 8; nt++)
#pragma unroll
        for (int e = 0; e < 2; e++) {
            int jj = warp_n * 64 + nt * 8 + cbase + e;
            float g = cacc[mt][nt][half * 2 + e];
            float d2 = fmaf(g, -2.0f, ci + cj[nt * 2 + e]);
            float d  = fast_sqrt(fmaxf(d2, 1e-12f));
            float h;
            bool boosted;
            if (FAST) {
                h = fmaf(d, e ? se1 : se0, e ? ce1 : ce0);
                boosted = brow && (jj == jtarget);
            } else {
                int ljv2 = lj[nt * 2 + e];
                h = (li == ljv2) ? (d - 0.1f) : (1.0f - d);
                boosted = brow && (li != ljv2) && (jj == jtarget);
            }
            h = fmaxf(h, 0.0f);
            if (MASK) {
                int I = i0 + ii, J = j0 + jj;
                h = (I > J && I < n) ? h : 0.0f;
            }
            float hh = h * h;
            if (e) ls1 += hh; else ls0 += hh;
            if (boosted) { if (e) ls3 += hh; else ls2 += hh; }
        }
    }
    return (ls0 + ls1) + (ls2 + ls3);
}

// fast epilogue (off-diagonal tiles, alternating labels): per thread there
// are 32 pos-parity slots (mt*half*nt) and 32 neg slots. Assumes every neg
// slot inactive (d2 >= 1) and every pos slot unclipped (d2 >= 0.01); verified
// by fmin chains, exact per-thread fallback otherwise. Boost pairs are neg
// pairs -> only matter when a neg slot is active -> covered by fallback.
__device__ __forceinline__ float epi_fast(const float (&cacc)[2][8][4],
                                          const char* sb, int warp_m, int warp_n,
                                          int lid, int i0, int j0, int n) {
    const float* cpv = (const float*)sb;
    const float* cmv = (const float*)(sb + 512);
    const int rbase = lid >> 2, cbase = (lid & 3) << 1;
    const int pi = rbase & 1;

    float cj[16];
#pragma unroll
    for (int k = 0; k < 16; k++)
        cj[k] = cmv[warp_n * 64 + (k >> 1) * 8 + cbase + (k & 1)];

    float td0 = 0.f, td1 = 0.f, t2a = 0.f, t2b = 0.f;
    float mnp = 1e30f, mnn = 1e30f;
#pragma unroll
    for (int mt = 0; mt < 2; mt++)
#pragma unroll
    for (int half = 0; half < 2; half++) {
        int ii = warp_m * 32 + mt * 16 + rbase + half * 8;
        float ci = cpv[ii];
#pragma unroll
        for (int nt = 0; nt < 8; nt++) {
            float g0 = cacc[mt][nt][half * 2 + 0];
            float g1 = cacc[mt][nt][half * 2 + 1];
            float d20 = fmaf(g0, -2.0f, ci + cj[nt * 2 + 0]);
            float d21 = fmaf(g1, -2.0f, ci + cj[nt * 2 + 1]);
            float d2p = pi ? d21 : d20;     // pos slot: e parity == pi
            float d2n = pi ? d20 : d21;
            mnp = fminf(mnp, d2p);
            mnn = fminf(mnn, d2n);
            d2p = fmaxf(d2p, 1e-12f);
            if (nt & 1) { td1 += fast_sqrt(d2p); t2b += d2p; }
            else        { td0 += fast_sqrt(d2p); t2a += d2p; }
        }
    }
    if (mnp < 0.01f || mnn < 1.0f)          // rare: exact per-thread redo
        return epilogue<false, true>(cacc, sb, warp_m, warp_n, lid, i0, j0, n);
    // 32 pos slots: sum (d-0.1)^2 = sum d2 - 0.2*sum d + 32*0.01
    return fmaf(td0 + td1, -0.2f, t2a + t2b) + 0.32f;
}

__global__ void __launch_bounds__(256, 1)
pair_kernel(int n, int ntiles, int gp) {
    extern __shared__ char sm[];
    const uint32_t smb = smem_u32(sm);

    const int tid = threadIdx.x, wid = tid >> 5, lid = tid & 31;
    const int warp_m = wid >> 1, warp_n = wid & 1;
    const int q = lid >> 3, rl = lid & 7;
    const int qh = q >> 1, ql = q & 1;
    const bool nmask_all = (n & (TM - 1)) != 0;

    // pattern flag: AND of per-slice flags written by prep
    int pat = 1;
    {
        const int nfb = nfb_of(n);
        for (int k = 0; k < nfb; k++) pat &= g_patv[k];
    }

    uint32_t rowA[2], r7A[2];
#pragma unroll
    for (int mt = 0; mt < 2; mt++) {
        int r = warp_m * 32 + mt * 16 + ql * 8 + rl;
        rowA[mt] = (uint32_t)r << 9;
        r7A[mt]  = (uint32_t)(r & 7);
    }
    uint32_t rowB[4], r7B[4];
#pragma unroll
    for (int p = 0; p < 4; p++) {
        int r = warp_n * 64 + p * 16 + qh * 8 + rl;
        rowB[p] = (uint32_t)r << 9;
        r7B[p]  = (uint32_t)(r & 7);
    }

    auto load_tile = [&](uint32_t dstbase, int row0) {
#pragma unroll
        for (int k = 0; k < 16; k++) {
            int idx = tid + (k << 8);
            int r = idx >> 5, c = idx & 31;
            uint32_t soff = ((uint32_t)r << 9) + (uint32_t)((c ^ (r & 7)) << 4);
            int gr = min(row0 + r, n - 1);
            cpasync16(dstbase + soff, &g_ebf[gr * D + (c << 3)]);
        }
    };
    auto load_stats = [&](int i0, int j0, int par) {
        if (tid < 128) {
            uint32_t sb = smb + OFF_ST + (uint32_t)par * 2048u;
            int grp = tid >> 5, l = tid & 31;
            if (grp >= 2 && pat) return;   // FAST path never reads labels
            const void* src;
            if      (grp == 0) src = &g_cp[min(i0 + l * 4, n - 4)];
            else if (grp == 1) src = &g_cm[min(j0 + l * 4, n - 4)];
            else if (grp == 2) src = &g_lab[min(i0 + l * 4, n - 4)];
            else               src = &g_lab[min(j0 + l * 4, n - 4)];
            cpasync16(sb + (uint32_t)grp * 512u + (uint32_t)l * 16u, src);
        }
    };

    const int base = ntiles / gp, rem = ntiles % gp;
    const int bid = blockIdx.x;
    const int tstart = bid * base + min(bid, rem);
    const int len = base + (bid < rem ? 1 : 0);
    const int tend = tstart + len;

    // ---- prologue ----
    int i0, j0, ni0 = 0, nj0 = 0;
    decode_tile(tstart, i0, j0);
    load_tile(smb + OFF_A, i0);
    load_tile(smb + OFF_B0, j0);
    load_stats(i0, j0, 0);
    CP_COMMIT();
    if (tstart + 1 < tend) {
        decode_tile(tstart + 1, ni0, nj0);
        load_tile(smb + OFF_B1, nj0);
        load_stats(ni0, nj0, 1);
    }
    CP_COMMIT();

    double acc = 0.0;
    for (int it = 0; it < len; it++) {
        const int t = tstart + it;
        CP_WAIT1();
        __syncthreads();

        const uint32_t Ab = smb + OFF_A;
        const uint32_t Bb = smb + ((it & 1) ? OFF_B1 : OFF_B0);

        float cacc[2][8][4];
#pragma unroll
        for (int mt = 0; mt < 2; mt++)
#pragma unroll
            for (int nt = 0; nt < 8; nt++)
#pragma unroll
                for (int e = 0; e < 4; e++) cacc[mt][nt][e] = 0.0f;

#pragma unroll
        for (int ks = 0; ks < 16; ks++) {
            const uint32_t cb = (uint32_t)(ks << 1);
            uint32_t Af[2][4];
#pragma unroll
            for (int mt = 0; mt < 2; mt++)
                ldsm4(Af[mt], Ab + rowA[mt] + (((cb + qh) ^ r7A[mt]) << 4));
#pragma unroll
            for (int p = 0; p < 4; p++) {
                uint32_t Bf[4];
                ldsm4(Bf, Bb + rowB[p] + (((cb + ql) ^ r7B[p]) << 4));
                mma16816(cacc[0][2 * p],     Af[0], Bf[0], Bf[1]);
                mma16816(cacc[1][2 * p],     Af[1], Bf[0], Bf[1]);
                mma16816(cacc[0][2 * p + 1], Af[0], Bf[2], Bf[3]);
                mma16816(cacc[1][2 * p + 1], Af[1], Bf[2], Bf[3]);
            }
        }

        {
            const char* sb = sm + OFF_ST + (size_t)(it & 1) * 2048;
            bool mask = (i0 == j0) || nmask_all;
            float lsum;
            if (pat) {
                if (mask) lsum = epilogue<true, true>(cacc, sb, warp_m, warp_n, lid, i0, j0, n);
                else      lsum = epi_fast(cacc, sb, warp_m, warp_n, lid, i0, j0, n);
            } else {
                lsum = mask ? epilogue<true,  false>(cacc, sb, warp_m, warp_n, lid, i0, j0, n)
                            : epilogue<false, false>(cacc, sb, warp_m, warp_n, lid, i0, j0, n);
            }
            acc += (double)lsum;
        }

        __syncthreads();

        if (it + 1 < len && ni0 != i0) load_tile(smb + OFF_A, ni0);
        CP_COMMIT();
        int m0 = 0, mj0 = 0;
        if ((t + 2) < tend) {
            decode_tile(t + 2, m0, mj0);
            load_tile(smb + ((it & 1) ? OFF_B1 : OFF_B0), mj0);
            load_stats(m0, mj0, it & 1);
        }
        CP_COMMIT();

        i0 = ni0; j0 = nj0;
        ni0 = m0; nj0 = mj0;
    }

    // deterministic reduction
#pragma unroll
    for (int o = 16; o > 0; o >>= 1)
        acc += __shfl_xor_sync(0xffffffffu, acc, o);
    __shared__ double sh_d[8];
    if (lid == 0) sh_d[wid] = acc;
    __syncthreads();
    if (tid == 0) {
        double tot = 0.0;
#pragma unroll
        for (int w = 0; w < 8; w++) tot += sh_d[w];
        g_part[blockIdx.x] = tot;
    }
}

// ---------------------------------------------------------------------------
__global__ void finalize_kernel(float* __restrict__ out, int n, int nparts) {
    int t = threadIdx.x;
    double s = 0.0;
    for (int i = t; i < nparts; i += 256) s += g_part[i];
#pragma unroll
    for (int o = 16; o > 0; o >>= 1)
        s += __shfl_xor_sync(0xffffffffu, s, o);
    __shared__ double sh[8];
    if ((t & 31) == 0) sh[t >> 5] = s;
    __syncthreads();
    if (t == 0) {
        double tot = 0.0;
#pragma unroll
        for (int w = 0; w < 8; w++) tot += sh[w];
        out[0] = (float)(0.5 * tot / (0.5 * (double)n * (double)(n - 1)));
    }
}

// ---------------------------------------------------------------------------
extern "C" void kernel_launch(void* const* d_in, const int* in_sizes, int n_in,
                              void* d_out, int out_size) {
    const float* emb = (const float*)d_in[0];
    const int*   lab = (const int*)d_in[1];   // dtype sniffed on-device
    int n = in_sizes[0] / D;

    cudaFuncSetAttribute(pair_kernel, cudaFuncAttributeMaxDynamicSharedMemorySize, SMEM_BYTES);

    prep_kernel<<<(n + 7) / 8, 256>>>(emb, lab, n);

    int nb = (n + TM - 1) / TM;
    int ntiles = nb * (nb + 1) / 2;
    int gp = min(GRID_PAIR, ntiles);
    pair_kernel<<<gp, 256, SMEM_BYTES>>>(n, ntiles, gp);

    finalize_kernel<<<1, 256>>>((float*)d_out, n, gp);
}